// round 13
// baseline (speedup 1.0000x reference)
#include <cuda_runtime.h>
#include <cuda_fp16.h>
#include <cstdint>
#include <math.h>

#define HID  512
#define NEXP 8
#define IMOE 1024
#define ISH  2048
#define TMAX 49152
#define PAIRMAX (2*TMAX)

// ---------------- device scratch ----------------
__device__ int   g_cnt[NEXP];
__device__ int   g_off[NEXP];
__device__ int   g_cursor[NEXP];
__device__ int   g_te[TMAX*2];
__device__ float g_tw[TMAX*2];
__device__ int   g_buck[PAIRMAX];
__device__ float g_slotw[PAIRMAX];
__device__ float g_sig[TMAX];

__device__ __half g_x  [(size_t)TMAX*HID];
__device__ __half g_w1t[(size_t)NEXP*IMOE*HID];
__device__ __half g_w3t[(size_t)NEXP*IMOE*HID];
__device__ __half g_w2t[(size_t)NEXP*HID*IMOE];
__device__ __half g_s1t[(size_t)ISH*HID];
__device__ __half g_s3t[(size_t)ISH*HID];
__device__ __half g_s2t[(size_t)HID*ISH];
__device__ __half g_ph [(size_t)PAIRMAX*IMOE];
__device__ __half g_sh [(size_t)TMAX*ISH];

// ---------------- helpers ----------------
__device__ __forceinline__ uint32_t smem_u32(const void* p) {
    uint32_t a;
    asm("{ .reg .u64 t; cvta.to.shared.u64 t, %1; cvt.u32.u64 %0, t; }" : "=r"(a) : "l"(p));
    return a;
}
__device__ __forceinline__ void cp16(uint32_t dst, const void* src) {
    asm volatile("cp.async.cg.shared.global [%0], [%1], 16;" :: "r"(dst), "l"(src));
}
__device__ __forceinline__ void cp_commit() { asm volatile("cp.async.commit_group;"); }
__device__ __forceinline__ void cp_wait1()  { asm volatile("cp.async.wait_group 1;"); }
__device__ __forceinline__ void cp_wait0()  { asm volatile("cp.async.wait_group 0;"); }

__device__ __forceinline__ void ldsm4(uint32_t r[4], uint32_t addr) {
    asm volatile("ldmatrix.sync.aligned.m8n8.x4.shared.b16 {%0,%1,%2,%3}, [%4];"
        : "=r"(r[0]), "=r"(r[1]), "=r"(r[2]), "=r"(r[3]) : "r"(addr));
}
__device__ __forceinline__ void mma_h(float c[4], const uint32_t a[4], uint32_t b0, uint32_t b1) {
    asm volatile("mma.sync.aligned.m16n8k16.row.col.f32.f16.f16.f32 "
        "{%0,%1,%2,%3}, {%4,%5,%6,%7}, {%8,%9}, {%0,%1,%2,%3};"
        : "+f"(c[0]), "+f"(c[1]), "+f"(c[2]), "+f"(c[3])
        : "r"(a[0]), "r"(a[1]), "r"(a[2]), "r"(a[3]), "r"(b0), "r"(b1));
}

// ---------------- routing ----------------
__global__ void k_zero() { if (threadIdx.x < NEXP) g_cnt[threadIdx.x] = 0; }

__global__ void k_router(const float* __restrict__ x, const float* __restrict__ gw,
                         const float* __restrict__ sg, float* __restrict__ logits, int T)
{
    int warp = (blockIdx.x * blockDim.x + threadIdx.x) >> 5;
    int lane = threadIdx.x & 31;
    if (warp >= T) return;
    const float* xp = x + (size_t)warp * HID;
    float acc[NEXP];
#pragma unroll
    for (int e = 0; e < NEXP; e++) acc[e] = 0.f;
    float ag = 0.f;
    for (int c = lane; c < HID; c += 32) {
        float xv = xp[c];
#pragma unroll
        for (int e = 0; e < NEXP; e++) acc[e] += xv * gw[c*NEXP + e];
        ag += xv * sg[c];
    }
#pragma unroll
    for (int o = 16; o > 0; o >>= 1) {
#pragma unroll
        for (int e = 0; e < NEXP; e++) acc[e] += __shfl_xor_sync(0xffffffffu, acc[e], o);
        ag += __shfl_xor_sync(0xffffffffu, ag, o);
    }
    if (lane == 0) {
        float mx = acc[0];
#pragma unroll
        for (int e = 1; e < NEXP; e++) mx = fmaxf(mx, acc[e]);
        float p[NEXP]; float s = 0.f;
#pragma unroll
        for (int e = 0; e < NEXP; e++) { p[e] = __expf(acc[e] - mx); s += p[e]; }
        int i0 = 0;
#pragma unroll
        for (int e = 1; e < NEXP; e++) if (acc[e] > acc[i0]) i0 = e;
        int i1 = (i0 == 0) ? 1 : 0;
#pragma unroll
        for (int e = 0; e < NEXP; e++) if (e != i0 && acc[e] > acc[i1]) i1 = e;
        float inv = 1.f / s;
        g_te[warp*2+0] = i0;  g_te[warp*2+1] = i1;
        g_tw[warp*2+0] = p[i0]*inv;  g_tw[warp*2+1] = p[i1]*inv;
        atomicAdd(&g_cnt[i0], 1);
        atomicAdd(&g_cnt[i1], 1);
        g_sig[warp] = 1.f / (1.f + __expf(-ag));
#pragma unroll
        for (int e = 0; e < NEXP; e++) logits[(size_t)warp*NEXP + e] = acc[e];
    }
}

__global__ void k_scan() {
    if (threadIdx.x == 0) {
        int o = 0;
        for (int e = 0; e < NEXP; e++) { g_off[e] = o; g_cursor[e] = o; o += g_cnt[e]; }
    }
}

__global__ void k_assign(int T) {
    int t = blockIdx.x * blockDim.x + threadIdx.x;
    if (t >= T) return;
#pragma unroll
    for (int k = 0; k < 2; k++) {
        int e = g_te[t*2+k];
        int pos = atomicAdd(&g_cursor[e], 1);
        g_buck[pos]  = t;
        g_slotw[pos] = g_tw[t*2+k];
    }
}

// ---------------- convert / transpose-convert ----------------
__global__ void k_cvt(const float* __restrict__ s, __half* __restrict__ d, long n)
{
    long i = (long)blockIdx.x * blockDim.x + threadIdx.x;
    if (i >= n) return;
    d[i] = __float2half_rn(s[i]);
}

// src [batch][R][C] -> dst [batch][C][R]
__global__ void k_tcvt(const float* __restrict__ src, __half* __restrict__ dst, int R, int C)
{
    __shared__ float t[32][33];
    size_t bo = (size_t)blockIdx.z * R * C;
    int c0 = blockIdx.x * 32, r0 = blockIdx.y * 32;
    int x = threadIdx.x, y = threadIdx.y;
#pragma unroll
    for (int i = 0; i < 32; i += 8)
        t[y+i][x] = src[bo + (size_t)(r0+y+i)*C + c0 + x];
    __syncthreads();
#pragma unroll
    for (int i = 0; i < 32; i += 8) {
        size_t di = bo + (size_t)(c0+y+i)*R + r0 + x;
        dst[di] = __float2half_rn(t[x][y+i]);
    }
}

// ============================================================
// GEMM: CTA tile M=128 x N=128, BK=32, 8 warps (4m x 2n), warp 32x64.
// rows padded to 80B in smem; cp.async double-buffered; fp16 HMMA, fp32 accum.
// ============================================================

#define STG_D 30720   // A (10240) + B1 (10240) + B3 (10240)
#define STG_S 20480   // A (10240) + B (10240)

// -------- DUAL: C1=A@B1, C3=A@B3, write silu(C1)*C3 as fp16 --------
__global__ void __launch_bounds__(256, 1)
gemm_dual(const __half* __restrict__ A,
          const __half* __restrict__ B1, const __half* __restrict__ B3,
          __half* __restrict__ O,
          int K, int NOUT, int moe, int Tn)
{
    int e = blockIdx.z;
    int rows = moe ? g_cnt[e] : Tn;
    int base = moe ? g_off[e] : 0;
    int m0 = blockIdx.x * 128;
    if (m0 >= rows) return;
    int n0 = blockIdx.y * 128;

    extern __shared__ char sm[];
    uint32_t sb = smem_u32(sm);
    unsigned long long* rowoff = (unsigned long long*)(sm + 2*STG_D);

    int tid = threadIdx.x, lane = tid & 31, wid = tid >> 5;
    int wm = wid >> 1, wn = wid & 1;

    if (tid < 128) {
        int r = m0 + tid; if (r >= rows) r = rows - 1;
        int gr = moe ? g_buck[base + r] : r;
        rowoff[tid] = (unsigned long long)gr * (unsigned long long)K;
    }
    __syncthreads();

    const __half* bS[2];
    {
        size_t eoff = (size_t)(moe ? e : 0) * NOUT;
        bS[0] = B1 + (eoff + n0) * K;
        bS[1] = B3 + (eoff + n0) * K;
    }

    int nk = K / 32;

    auto load_stage = [&](int s, int k0) {
        uint32_t sbase = sb + (uint32_t)(s & 1) * STG_D;
#pragma unroll
        for (int i = 0; i < 2; i++) {                 // A: 512 chunks
            int c = tid + 256*i;
            int row = c >> 2, ch = c & 3;
            cp16(sbase + row*80 + ch*16, A + rowoff[row] + k0 + ch*8);
        }
#pragma unroll
        for (int m = 0; m < 2; m++)                   // B1, B3: 512 chunks each
#pragma unroll
            for (int i = 0; i < 2; i++) {
                int c = tid + 256*i;
                int row = c >> 2, ch = c & 3;
                cp16(sbase + 10240 + m*10240 + row*80 + ch*16,
                     bS[m] + (size_t)row * K + k0 + ch*8);
            }
        cp_commit();
    };

    float c1[2][8][4], c3[2][8][4];
#pragma unroll
    for (int a = 0; a < 2; a++)
#pragma unroll
        for (int b = 0; b < 8; b++)
#pragma unroll
            for (int d = 0; d < 4; d++) { c1[a][b][d] = 0.f; c3[a][b][d] = 0.f; }

    uint32_t aRow = (uint32_t)((wm*32 + (lane & 15))*80 + (lane >> 4)*16);
    uint32_t bRow = (uint32_t)((wn*64 + (lane & 7) + ((lane >> 4) & 1)*8)*80 + ((lane >> 3) & 1)*16);

    load_stage(0, 0);
    for (int ks = 0; ks < nk; ks++) {
        if (ks + 1 < nk) { load_stage(ks+1, (ks+1)*32); cp_wait1(); }
        else cp_wait0();
        __syncthreads();
        uint32_t sbase = sb + (uint32_t)(ks & 1) * STG_D;
#pragma unroll
        for (int k16 = 0; k16 < 2; k16++) {
            uint32_t koff = k16*32;
            uint32_t a[2][4];
#pragma unroll
            for (int mt = 0; mt < 2; mt++)
                ldsm4(a[mt], sbase + aRow + mt*1280 + koff);
            uint32_t b1[4][4], b3[4][4];
#pragma unroll
            for (int p = 0; p < 4; p++) {
                ldsm4(b1[p], sbase + 10240 +       bRow + p*1280 + koff);
                ldsm4(b3[p], sbase + 10240+10240 + bRow + p*1280 + koff);
            }
#pragma unroll
            for (int mt = 0; mt < 2; mt++)
#pragma unroll
                for (int nt = 0; nt < 8; nt++) {
                    int p = nt >> 1, q = (nt & 1)*2;
                    mma_h(c1[mt][nt], a[mt], b1[p][q], b1[p][q+1]);
                    mma_h(c3[mt][nt], a[mt], b3[p][q], b3[p][q+1]);
                }
        }
        __syncthreads();
    }

    // epilogue: h = silu(c1)*c3 -> fp16
#pragma unroll
    for (int mt = 0; mt < 2; mt++)
#pragma unroll
        for (int nt = 0; nt < 8; nt++) {
            int col = n0 + wn*64 + nt*8 + (lane & 3)*2;
#pragma unroll
            for (int half = 0; half < 2; half++) {
                int rloc = wm*32 + mt*16 + (lane >> 2) + half*8;
                int r = m0 + rloc;
                if (r < rows) {
                    float d1a = c1[mt][nt][half*2],   d3a = c3[mt][nt][half*2];
                    float d1b = c1[mt][nt][half*2+1], d3b = c3[mt][nt][half*2+1];
                    float ha = d1a / (1.f + __expf(-d1a)) * d3a;
                    float hb = d1b / (1.f + __expf(-d1b)) * d3b;
                    size_t o = (size_t)(base + r) * NOUT + col;
                    *(__half2*)(O + o) = __floats2half2_rn(ha, hb);
                }
            }
        }
}

// -------- SINGLE: C = A@B, add into out (atomic for moe) --------
__global__ void __launch_bounds__(256, 1)
gemm_single(const __half* __restrict__ A, const __half* __restrict__ B,
            float* __restrict__ out, int K, int moe, int Tn)
{
    int e = blockIdx.z;
    int rows = moe ? g_cnt[e] : Tn;
    int base = moe ? g_off[e] : 0;
    int m0 = blockIdx.x * 128;
    if (m0 >= rows) return;
    int n0 = blockIdx.y * 128;

    extern __shared__ char sm[];
    uint32_t sb = smem_u32(sm);
    unsigned long long* rowoff = (unsigned long long*)(sm + 2*STG_S);

    int tid = threadIdx.x, lane = tid & 31, wid = tid >> 5;
    int wm = wid >> 1, wn = wid & 1;

    if (tid < 128) {
        int r = m0 + tid; if (r >= rows) r = rows - 1;
        rowoff[tid] = (unsigned long long)(base + r) * (unsigned long long)K;
    }
    __syncthreads();

    const __half* bP = B + ((size_t)(moe ? e : 0) * HID + n0) * K;

    int nk = K / 32;

    auto load_stage = [&](int s, int k0) {
        uint32_t sbase = sb + (uint32_t)(s & 1) * STG_S;
#pragma unroll
        for (int i = 0; i < 2; i++) {
            int c = tid + 256*i;
            int row = c >> 2, ch = c & 3;
            cp16(sbase + row*80 + ch*16, A + rowoff[row] + k0 + ch*8);
        }
#pragma unroll
        for (int i = 0; i < 2; i++) {
            int c = tid + 256*i;
            int row = c >> 2, ch = c & 3;
            cp16(sbase + 10240 + row*80 + ch*16, bP + (size_t)row * K + k0 + ch*8);
        }
        cp_commit();
    };

    float cc[2][8][4];
#pragma unroll
    for (int a = 0; a < 2; a++)
#pragma unroll
        for (int b = 0; b < 8; b++)
#pragma unroll
            for (int d = 0; d < 4; d++) cc[a][b][d] = 0.f;

    uint32_t aRow = (uint32_t)((wm*32 + (lane & 15))*80 + (lane >> 4)*16);
    uint32_t bRow = (uint32_t)((wn*64 + (lane & 7) + ((lane >> 4) & 1)*8)*80 + ((lane >> 3) & 1)*16);

    load_stage(0, 0);
    for (int ks = 0; ks < nk; ks++) {
        if (ks + 1 < nk) { load_stage(ks+1, (ks+1)*32); cp_wait1(); }
        else cp_wait0();
        __syncthreads();
        uint32_t sbase = sb + (uint32_t)(ks & 1) * STG_S;
#pragma unroll
        for (int k16 = 0; k16 < 2; k16++) {
            uint32_t koff = k16*32;
            uint32_t a[2][4];
#pragma unroll
            for (int mt = 0; mt < 2; mt++)
                ldsm4(a[mt], sbase + aRow + mt*1280 + koff);
            uint32_t b[4][4];
#pragma unroll
            for (int p = 0; p < 4; p++)
                ldsm4(b[p], sbase + 10240 + bRow + p*1280 + koff);
#pragma unroll
            for (int mt = 0; mt < 2; mt++)
#pragma unroll
                for (int nt = 0; nt < 8; nt++) {
                    int p = nt >> 1, q = (nt & 1)*2;
                    mma_h(cc[mt][nt], a[mt], b[p][q], b[p][q+1]);
                }
        }
        __syncthreads();
    }

#pragma unroll
    for (int mt = 0; mt < 2; mt++)
#pragma unroll
        for (int nt = 0; nt < 8; nt++) {
            int col = n0 + wn*64 + nt*8 + (lane & 3)*2;
#pragma unroll
            for (int half = 0; half < 2; half++) {
                int rloc = wm*32 + mt*16 + (lane >> 2) + half*8;
                int r = m0 + rloc;
                if (r < rows) {
                    float v0 = cc[mt][nt][half*2];
                    float v1 = cc[mt][nt][half*2+1];
                    if (moe) {
                        int slot = base + r;
                        int tok = g_buck[slot];
                        float w = g_slotw[slot];
                        float* op = out + (size_t)tok * HID + col;
                        atomicAdd(&op[0], w * v0);
                        atomicAdd(&op[1], w * v1);
                    } else {
                        float sgl = g_sig[r];
                        float* op = out + (size_t)r * HID + col;
                        op[0] += sgl * v0;
                        op[1] += sgl * v1;
                    }
                }
            }
        }
}

// ---------------- launch ----------------
extern "C" void kernel_launch(void* const* d_in, const int* in_sizes, int n_in,
                              void* d_out, int out_size)
{
    const float* x   = (const float*)d_in[0];
    const float* gw  = (const float*)d_in[1];
    const float* w1  = (const float*)d_in[2];
    const float* w2  = (const float*)d_in[3];
    const float* w3  = (const float*)d_in[4];
    const float* sw1 = (const float*)d_in[5];
    const float* sw2 = (const float*)d_in[6];
    const float* sw3 = (const float*)d_in[7];
    const float* sg  = (const float*)d_in[8];

    int T = in_sizes[0] / HID;
    if (T > TMAX) T = TMAX;

    float* out    = (float*)d_out;
    float* logits = out + (size_t)T * HID;

    const int SMD = 2*STG_D + 1024;   // 62464
    const int SMS = 2*STG_S + 1024;   // 41984
    cudaFuncSetAttribute(gemm_dual,   cudaFuncAttributeMaxDynamicSharedMemorySize, SMD);
    cudaFuncSetAttribute(gemm_single, cudaFuncAttributeMaxDynamicSharedMemorySize, SMS);

    cudaMemsetAsync(out, 0, (size_t)T * HID * sizeof(float));

    k_zero<<<1, 32>>>();
    k_router<<<(T + 3) / 4, 128>>>(x, gw, sg, logits, T);
    k_scan<<<1, 32>>>();
    k_assign<<<(T + 255) / 256, 256>>>(T);

    __half *xh, *w1t, *w3t, *w2t, *s1t, *s3t, *s2t, *ph, *sh;
    cudaGetSymbolAddress((void**)&xh,  g_x);
    cudaGetSymbolAddress((void**)&w1t, g_w1t);
    cudaGetSymbolAddress((void**)&w3t, g_w3t);
    cudaGetSymbolAddress((void**)&w2t, g_w2t);
    cudaGetSymbolAddress((void**)&s1t, g_s1t);
    cudaGetSymbolAddress((void**)&s3t, g_s3t);
    cudaGetSymbolAddress((void**)&s2t, g_s2t);
    cudaGetSymbolAddress((void**)&ph,  g_ph);
    cudaGetSymbolAddress((void**)&sh,  g_sh);

    {
        long n = (long)T * HID;
        k_cvt<<<(unsigned)((n + 255)/256), 256>>>(x, xh, n);
    }
    {
        dim3 blk(32, 8);
        k_tcvt<<<dim3(IMOE/32, HID/32, NEXP), blk>>>(w1, w1t, HID, IMOE);
        k_tcvt<<<dim3(IMOE/32, HID/32, NEXP), blk>>>(w3, w3t, HID, IMOE);
        k_tcvt<<<dim3(HID/32, IMOE/32, NEXP), blk>>>(w2, w2t, IMOE, HID);
        k_tcvt<<<dim3(ISH/32, HID/32, 1), blk>>>(sw1, s1t, HID, ISH);
        k_tcvt<<<dim3(ISH/32, HID/32, 1), blk>>>(sw3, s3t, HID, ISH);
        k_tcvt<<<dim3(HID/32, ISH/32, 1), blk>>>(sw2, s2t, ISH, HID);
    }

    int mt = (T + 127) / 128;   // 384

    // MoE FFN1: pairH = silu(Xg@W1)*(Xg@W3)
    gemm_dual<<<dim3(mt, IMOE/128, NEXP), 256, SMD>>>(
        xh, w1t, w3t, ph, HID, IMOE, 1, T);
    // MoE FFN2: out += w * pairH@W2
    gemm_single<<<dim3(mt, HID/128, NEXP), 256, SMS>>>(
        ph, w2t, out, IMOE, 1, T);
    // Shared FFN1
    gemm_dual<<<dim3(mt, ISH/128, 1), 256, SMD>>>(
        xh, s1t, s3t, sh, HID, ISH, 0, T);
    // Shared FFN2
    gemm_single<<<dim3(mt, HID/128, 1), 256, SMS>>>(
        sh, s2t, out, ISH, 0, T);
}

// round 15
// speedup vs baseline: 1.3005x; 1.3005x over previous
#include <cuda_runtime.h>
#include <cuda_fp16.h>
#include <cstdint>
#include <math.h>

#define HID  512
#define NEXP 8
#define IMOE 1024
#define ISH  2048
#define TMAX 49152
#define PAIRMAX (2*TMAX)

// ---------------- device scratch ----------------
__device__ int   g_cnt[NEXP];
__device__ int   g_off[NEXP];
__device__ int   g_cursor[NEXP];
__device__ int   g_te[TMAX*2];
__device__ float g_tw[TMAX*2];
__device__ int   g_buck[PAIRMAX];
__device__ float g_slotw[PAIRMAX];
__device__ float g_sig[TMAX];

__device__ __half g_x  [(size_t)TMAX*HID];
__device__ __half g_w1t[(size_t)NEXP*IMOE*HID];
__device__ __half g_w3t[(size_t)NEXP*IMOE*HID];
__device__ __half g_w2t[(size_t)NEXP*HID*IMOE];
__device__ __half g_s1t[(size_t)ISH*HID];
__device__ __half g_s3t[(size_t)ISH*HID];
__device__ __half g_s2t[(size_t)HID*ISH];
__device__ __half g_ph [(size_t)PAIRMAX*IMOE];
__device__ __half g_sh [(size_t)TMAX*ISH];

// ---------------- helpers ----------------
__device__ __forceinline__ uint32_t smem_u32(const void* p) {
    uint32_t a;
    asm("{ .reg .u64 t; cvta.to.shared.u64 t, %1; cvt.u32.u64 %0, t; }" : "=r"(a) : "l"(p));
    return a;
}
__device__ __forceinline__ void cp16(uint32_t dst, const void* src) {
    asm volatile("cp.async.cg.shared.global [%0], [%1], 16;" :: "r"(dst), "l"(src));
}
__device__ __forceinline__ void cp_commit() { asm volatile("cp.async.commit_group;"); }
__device__ __forceinline__ void cp_wait1()  { asm volatile("cp.async.wait_group 1;"); }
__device__ __forceinline__ void cp_wait0()  { asm volatile("cp.async.wait_group 0;"); }

__device__ __forceinline__ void ldsm4(uint32_t r[4], uint32_t addr) {
    asm volatile("ldmatrix.sync.aligned.m8n8.x4.shared.b16 {%0,%1,%2,%3}, [%4];"
        : "=r"(r[0]), "=r"(r[1]), "=r"(r[2]), "=r"(r[3]) : "r"(addr));
}
__device__ __forceinline__ void mma_h(float c[4], const uint32_t a[4], uint32_t b0, uint32_t b1) {
    asm volatile("mma.sync.aligned.m16n8k16.row.col.f32.f16.f16.f32 "
        "{%0,%1,%2,%3}, {%4,%5,%6,%7}, {%8,%9}, {%0,%1,%2,%3};"
        : "+f"(c[0]), "+f"(c[1]), "+f"(c[2]), "+f"(c[3])
        : "r"(a[0]), "r"(a[1]), "r"(a[2]), "r"(a[3]), "r"(b0), "r"(b1));
}

// ---------------- routing ----------------
__global__ void k_zero() { if (threadIdx.x < NEXP) g_cnt[threadIdx.x] = 0; }

__global__ void k_router(const float* __restrict__ x, const float* __restrict__ gw,
                         const float* __restrict__ sg, float* __restrict__ logits, int T)
{
    int warp = (blockIdx.x * blockDim.x + threadIdx.x) >> 5;
    int lane = threadIdx.x & 31;
    if (warp >= T) return;
    const float* xp = x + (size_t)warp * HID;
    float acc[NEXP];
#pragma unroll
    for (int e = 0; e < NEXP; e++) acc[e] = 0.f;
    float ag = 0.f;
    for (int c = lane; c < HID; c += 32) {
        float xv = xp[c];
#pragma unroll
        for (int e = 0; e < NEXP; e++) acc[e] += xv * gw[c*NEXP + e];
        ag += xv * sg[c];
    }
#pragma unroll
    for (int o = 16; o > 0; o >>= 1) {
#pragma unroll
        for (int e = 0; e < NEXP; e++) acc[e] += __shfl_xor_sync(0xffffffffu, acc[e], o);
        ag += __shfl_xor_sync(0xffffffffu, ag, o);
    }
    if (lane == 0) {
        float mx = acc[0];
#pragma unroll
        for (int e = 1; e < NEXP; e++) mx = fmaxf(mx, acc[e]);
        float p[NEXP]; float s = 0.f;
#pragma unroll
        for (int e = 0; e < NEXP; e++) { p[e] = __expf(acc[e] - mx); s += p[e]; }
        int i0 = 0;
#pragma unroll
        for (int e = 1; e < NEXP; e++) if (acc[e] > acc[i0]) i0 = e;
        int i1 = (i0 == 0) ? 1 : 0;
#pragma unroll
        for (int e = 0; e < NEXP; e++) if (e != i0 && acc[e] > acc[i1]) i1 = e;
        float inv = 1.f / s;
        g_te[warp*2+0] = i0;  g_te[warp*2+1] = i1;
        g_tw[warp*2+0] = p[i0]*inv;  g_tw[warp*2+1] = p[i1]*inv;
        atomicAdd(&g_cnt[i0], 1);
        atomicAdd(&g_cnt[i1], 1);
        g_sig[warp] = 1.f / (1.f + __expf(-ag));
#pragma unroll
        for (int e = 0; e < NEXP; e++) logits[(size_t)warp*NEXP + e] = acc[e];
    }
}

__global__ void k_scan() {
    if (threadIdx.x == 0) {
        int o = 0;
        for (int e = 0; e < NEXP; e++) { g_off[e] = o; g_cursor[e] = o; o += g_cnt[e]; }
    }
}

__global__ void k_assign(int T) {
    int t = blockIdx.x * blockDim.x + threadIdx.x;
    if (t >= T) return;
#pragma unroll
    for (int k = 0; k < 2; k++) {
        int e = g_te[t*2+k];
        int pos = atomicAdd(&g_cursor[e], 1);
        g_buck[pos]  = t;
        g_slotw[pos] = g_tw[t*2+k];
    }
}

// ---------------- convert / transpose-convert ----------------
__global__ void k_cvt(const float* __restrict__ s, __half* __restrict__ d, long n)
{
    long i = (long)blockIdx.x * blockDim.x + threadIdx.x;
    if (i >= n) return;
    d[i] = __float2half_rn(s[i]);
}

// src [batch][R][C] -> dst [batch][C][R]
__global__ void k_tcvt(const float* __restrict__ src, __half* __restrict__ dst, int R, int C)
{
    __shared__ float t[32][33];
    size_t bo = (size_t)blockIdx.z * R * C;
    int c0 = blockIdx.x * 32, r0 = blockIdx.y * 32;
    int x = threadIdx.x, y = threadIdx.y;
#pragma unroll
    for (int i = 0; i < 32; i += 8)
        t[y+i][x] = src[bo + (size_t)(r0+y+i)*C + c0 + x];
    __syncthreads();
#pragma unroll
    for (int i = 0; i < 32; i += 8) {
        size_t di = bo + (size_t)(c0+y+i)*R + r0 + x;
        dst[di] = __float2half_rn(t[x][y+i]);
    }
}

// ============================================================
// GEMM: CTA tile M=128 x N=64, BK=32, 8 warps (4m x 2n), warp 32x32.
// GRID: blockIdx.x = n-tile (fast), blockIdx.y = m-tile -> A-tile L2 reuse.
// rows padded to 80B in smem; cp.async double-buffered; fp16 HMMA, fp32 accum.
// ============================================================

#define STG_D 20480   // A (10240) + B1 (5120) + B3 (5120)
#define STG_S 15360   // A (10240) + B (5120)

// -------- DUAL: C1=A@B1, C3=A@B3, write silu(C1)*C3 as fp16 --------
__global__ void __launch_bounds__(256)
gemm_dual(const __half* __restrict__ A,
          const __half* __restrict__ B1, const __half* __restrict__ B3,
          __half* __restrict__ O,
          int K, int NOUT, int moe, int Tn)
{
    int e = blockIdx.z;
    int rows = moe ? g_cnt[e] : Tn;
    int base = moe ? g_off[e] : 0;
    int m0 = blockIdx.y * 128;
    if (m0 >= rows) return;
    int n0 = blockIdx.x * 64;

    extern __shared__ char sm[];
    uint32_t sb = smem_u32(sm);
    unsigned long long* rowoff = (unsigned long long*)(sm + 2*STG_D);

    int tid = threadIdx.x, lane = tid & 31, wid = tid >> 5;
    int wm = wid >> 1, wn = wid & 1;

    if (tid < 128) {
        int r = m0 + tid; if (r >= rows) r = rows - 1;
        int gr = moe ? g_buck[base + r] : r;
        rowoff[tid] = (unsigned long long)gr * (unsigned long long)K;
    }
    __syncthreads();

    const __half* bS[2];
    {
        size_t eoff = (size_t)(moe ? e : 0) * NOUT;
        bS[0] = B1 + (eoff + n0) * K;
        bS[1] = B3 + (eoff + n0) * K;
    }

    int nk = K / 32;

    auto load_stage = [&](int s, int k0) {
        uint32_t sbase = sb + (uint32_t)(s & 1) * STG_D;
#pragma unroll
        for (int i = 0; i < 2; i++) {                 // A: 512 chunks
            int c = tid + 256*i;
            int row = c >> 2, ch = c & 3;
            cp16(sbase + row*80 + ch*16, A + rowoff[row] + k0 + ch*8);
        }
#pragma unroll
        for (int i = 0; i < 2; i++) {                 // B: 2 mats x 256 chunks
            int c = tid + 256*i;
            int mh = c >> 8, row = (c >> 2) & 63, ch = c & 3;
            cp16(sbase + 10240 + mh*5120 + row*80 + ch*16,
                 bS[mh] + (size_t)row * K + k0 + ch*8);
        }
        cp_commit();
    };

    float c1[2][4][4], c3[2][4][4];
#pragma unroll
    for (int a = 0; a < 2; a++)
#pragma unroll
        for (int b = 0; b < 4; b++)
#pragma unroll
            for (int d = 0; d < 4; d++) { c1[a][b][d] = 0.f; c3[a][b][d] = 0.f; }

    uint32_t aRow = (uint32_t)((wm*32 + (lane & 15))*80 + (lane >> 4)*16);
    uint32_t bRow = (uint32_t)((wn*32 + (lane & 7) + ((lane >> 4) & 1)*8)*80 + ((lane >> 3) & 1)*16);

    load_stage(0, 0);
    for (int ks = 0; ks < nk; ks++) {
        if (ks + 1 < nk) { load_stage(ks+1, (ks+1)*32); cp_wait1(); }
        else cp_wait0();
        __syncthreads();
        uint32_t sbase = sb + (uint32_t)(ks & 1) * STG_D;
#pragma unroll
        for (int k16 = 0; k16 < 2; k16++) {
            uint32_t koff = k16*32;
            uint32_t a[2][4];
#pragma unroll
            for (int mt = 0; mt < 2; mt++)
                ldsm4(a[mt], sbase + aRow + mt*1280 + koff);
            uint32_t b1[2][4], b3[2][4];
#pragma unroll
            for (int p = 0; p < 2; p++) {
                ldsm4(b1[p], sbase + 10240 + 0*5120 + bRow + p*1280 + koff);
                ldsm4(b3[p], sbase + 10240 + 1*5120 + bRow + p*1280 + koff);
            }
#pragma unroll
            for (int mt = 0; mt < 2; mt++)
#pragma unroll
                for (int nt = 0; nt < 4; nt++) {
                    int p = nt >> 1, q = (nt & 1)*2;
                    mma_h(c1[mt][nt], a[mt], b1[p][q], b1[p][q+1]);
                    mma_h(c3[mt][nt], a[mt], b3[p][q], b3[p][q+1]);
                }
        }
        __syncthreads();
    }

    // epilogue: h = silu(c1)*c3 -> fp16
#pragma unroll
    for (int mt = 0; mt < 2; mt++)
#pragma unroll
        for (int nt = 0; nt < 4; nt++) {
            int col = n0 + wn*32 + nt*8 + (lane & 3)*2;
#pragma unroll
            for (int half = 0; half < 2; half++) {
                int rloc = wm*32 + mt*16 + (lane >> 2) + half*8;
                int r = m0 + rloc;
                if (r < rows) {
                    float d1a = c1[mt][nt][half*2],   d3a = c3[mt][nt][half*2];
                    float d1b = c1[mt][nt][half*2+1], d3b = c3[mt][nt][half*2+1];
                    float ha = d1a / (1.f + __expf(-d1a)) * d3a;
                    float hb = d1b / (1.f + __expf(-d1b)) * d3b;
                    size_t o = (size_t)(base + r) * NOUT + col;
                    *(__half2*)(O + o) = __floats2half2_rn(ha, hb);
                }
            }
        }
}

// -------- SINGLE: C = A@B, add into out (atomic for moe) --------
__global__ void __launch_bounds__(256)
gemm_single(const __half* __restrict__ A, const __half* __restrict__ B,
            float* __restrict__ out, int K, int moe, int Tn)
{
    int e = blockIdx.z;
    int rows = moe ? g_cnt[e] : Tn;
    int base = moe ? g_off[e] : 0;
    int m0 = blockIdx.y * 128;
    if (m0 >= rows) return;
    int n0 = blockIdx.x * 64;

    extern __shared__ char sm[];
    uint32_t sb = smem_u32(sm);
    unsigned long long* rowoff = (unsigned long long*)(sm + 2*STG_S);

    int tid = threadIdx.x, lane = tid & 31, wid = tid >> 5;
    int wm = wid >> 1, wn = wid & 1;

    if (tid < 128) {
        int r = m0 + tid; if (r >= rows) r = rows - 1;
        rowoff[tid] = (unsigned long long)(base + r) * (unsigned long long)K;
    }
    __syncthreads();

    const __half* bP = B + ((size_t)(moe ? e : 0) * HID + n0) * K;

    int nk = K / 32;

    auto load_stage = [&](int s, int k0) {
        uint32_t sbase = sb + (uint32_t)(s & 1) * STG_S;
#pragma unroll
        for (int i = 0; i < 2; i++) {
            int c = tid + 256*i;
            int row = c >> 2, ch = c & 3;
            cp16(sbase + row*80 + ch*16, A + rowoff[row] + k0 + ch*8);
        }
        {
            int c = tid;
            int row = (c >> 2) & 63, ch = c & 3;
            cp16(sbase + 10240 + row*80 + ch*16, bP + (size_t)row * K + k0 + ch*8);
        }
        cp_commit();
    };

    float cc[2][4][4];
#pragma unroll
    for (int a = 0; a < 2; a++)
#pragma unroll
        for (int b = 0; b < 4; b++)
#pragma unroll
            for (int d = 0; d < 4; d++) cc[a][b][d] = 0.f;

    uint32_t aRow = (uint32_t)((wm*32 + (lane & 15))*80 + (lane >> 4)*16);
    uint32_t bRow = (uint32_t)((wn*32 + (lane & 7) + ((lane >> 4) & 1)*8)*80 + ((lane >> 3) & 1)*16);

    load_stage(0, 0);
    for (int ks = 0; ks < nk; ks++) {
        if (ks + 1 < nk) { load_stage(ks+1, (ks+1)*32); cp_wait1(); }
        else cp_wait0();
        __syncthreads();
        uint32_t sbase = sb + (uint32_t)(ks & 1) * STG_S;
#pragma unroll
        for (int k16 = 0; k16 < 2; k16++) {
            uint32_t koff = k16*32;
            uint32_t a[2][4];
#pragma unroll
            for (int mt = 0; mt < 2; mt++)
                ldsm4(a[mt], sbase + aRow + mt*1280 + koff);
            uint32_t b[2][4];
#pragma unroll
            for (int p = 0; p < 2; p++)
                ldsm4(b[p], sbase + 10240 + bRow + p*1280 + koff);
#pragma unroll
            for (int mt = 0; mt < 2; mt++)
#pragma unroll
                for (int nt = 0; nt < 4; nt++) {
                    int p = nt >> 1, q = (nt & 1)*2;
                    mma_h(cc[mt][nt], a[mt], b[p][q], b[p][q+1]);
                }
        }
        __syncthreads();
    }

#pragma unroll
    for (int mt = 0; mt < 2; mt++)
#pragma unroll
        for (int nt = 0; nt < 4; nt++) {
            int col = n0 + wn*32 + nt*8 + (lane & 3)*2;
#pragma unroll
            for (int half = 0; half < 2; half++) {
                int rloc = wm*32 + mt*16 + (lane >> 2) + half*8;
                int r = m0 + rloc;
                if (r < rows) {
                    float v0 = cc[mt][nt][half*2];
                    float v1 = cc[mt][nt][half*2+1];
                    if (moe) {
                        int slot = base + r;
                        int tok = g_buck[slot];
                        float w = g_slotw[slot];
                        float* op = out + (size_t)tok * HID + col;
                        atomicAdd(&op[0], w * v0);
                        atomicAdd(&op[1], w * v1);
                    } else {
                        float sgl = g_sig[r];
                        float* op = out + (size_t)r * HID + col;
                        op[0] += sgl * v0;
                        op[1] += sgl * v1;
                    }
                }
            }
        }
}

// ---------------- launch ----------------
extern "C" void kernel_launch(void* const* d_in, const int* in_sizes, int n_in,
                              void* d_out, int out_size)
{
    const float* x   = (const float*)d_in[0];
    const float* gw  = (const float*)d_in[1];
    const float* w1  = (const float*)d_in[2];
    const float* w2  = (const float*)d_in[3];
    const float* w3  = (const float*)d_in[4];
    const float* sw1 = (const float*)d_in[5];
    const float* sw2 = (const float*)d_in[6];
    const float* sw3 = (const float*)d_in[7];
    const float* sg  = (const float*)d_in[8];

    int T = in_sizes[0] / HID;
    if (T > TMAX) T = TMAX;

    float* out    = (float*)d_out;
    float* logits = out + (size_t)T * HID;

    const int SMD = 2*STG_D + 1024;   // 41984
    const int SMS = 2*STG_S + 1024;   // 31744
    cudaFuncSetAttribute(gemm_dual,   cudaFuncAttributeMaxDynamicSharedMemorySize, SMD);
    cudaFuncSetAttribute(gemm_single, cudaFuncAttributeMaxDynamicSharedMemorySize, SMS);

    cudaMemsetAsync(out, 0, (size_t)T * HID * sizeof(float));

    k_zero<<<1, 32>>>();
    k_router<<<(T + 3) / 4, 128>>>(x, gw, sg, logits, T);
    k_scan<<<1, 32>>>();
    k_assign<<<(T + 255) / 256, 256>>>(T);

    __half *xh, *w1t, *w3t, *w2t, *s1t, *s3t, *s2t, *ph, *sh;
    cudaGetSymbolAddress((void**)&xh,  g_x);
    cudaGetSymbolAddress((void**)&w1t, g_w1t);
    cudaGetSymbolAddress((void**)&w3t, g_w3t);
    cudaGetSymbolAddress((void**)&w2t, g_w2t);
    cudaGetSymbolAddress((void**)&s1t, g_s1t);
    cudaGetSymbolAddress((void**)&s3t, g_s3t);
    cudaGetSymbolAddress((void**)&s2t, g_s2t);
    cudaGetSymbolAddress((void**)&ph,  g_ph);
    cudaGetSymbolAddress((void**)&sh,  g_sh);

    {
        long n = (long)T * HID;
        k_cvt<<<(unsigned)((n + 255)/256), 256>>>(x, xh, n);
    }
    {
        dim3 blk(32, 8);
        k_tcvt<<<dim3(IMOE/32, HID/32, NEXP), blk>>>(w1, w1t, HID, IMOE);
        k_tcvt<<<dim3(IMOE/32, HID/32, NEXP), blk>>>(w3, w3t, HID, IMOE);
        k_tcvt<<<dim3(HID/32, IMOE/32, NEXP), blk>>>(w2, w2t, IMOE, HID);
        k_tcvt<<<dim3(ISH/32, HID/32, 1), blk>>>(sw1, s1t, HID, ISH);
        k_tcvt<<<dim3(ISH/32, HID/32, 1), blk>>>(sw3, s3t, HID, ISH);
        k_tcvt<<<dim3(HID/32, ISH/32, 1), blk>>>(sw2, s2t, ISH, HID);
    }

    int mt = (T + 127) / 128;   // 384

    // grid: x = n-tiles (fast -> L2 A-reuse), y = m-tiles, z = experts
    // MoE FFN1: pairH = silu(Xg@W1)*(Xg@W3)
    gemm_dual<<<dim3(IMOE/64, mt, NEXP), 256, SMD>>>(
        xh, w1t, w3t, ph, HID, IMOE, 1, T);
    // MoE FFN2: out += w * pairH@W2
    gemm_single<<<dim3(HID/64, mt, NEXP), 256, SMS>>>(
        ph, w2t, out, IMOE, 1, T);
    // Shared FFN1
    gemm_dual<<<dim3(ISH/64, mt, 1), 256, SMD>>>(
        xh, s1t, s3t, sh, HID, ISH, 0, T);
    // Shared FFN2
    gemm_single<<<dim3(HID/64, mt, 1), 256, SMS>>>(
        sh, s2t, out, ISH, 0, T);
}